// round 1
// baseline (speedup 1.0000x reference)
#include <cuda_runtime.h>
#include <cuda_bf16.h>
#include <math.h>

// Problem constants
#define BB   2
#define TT   2048
#define CC   1024
#define NH   16
#define DH   64
#define NTOK (BB * TT)          // 4096
#define C3   (3 * CC)           // 3072

// ---------------------------------------------------------------------------
// Scratch (static device globals: allocation-guard safe)
// ---------------------------------------------------------------------------
__device__ float g_qkv[NTOK * C3];   // (b*T+t, 3*C)  Q at +0, K at +1024, V at +2048
__device__ float g_y[NTOK * CC];     // attention output in (b,t, h*64+d) layout

// ---------------------------------------------------------------------------
// SGEMM with fused bias:  C[M,N] = A[M,K] @ B[K,N] + bias[N]
// BM=BN=128, BK=8, 256 threads, 8x8 per-thread microtile.
// All dims here are multiples of the tile sizes; no bounds checks needed.
// ---------------------------------------------------------------------------
__global__ void __launch_bounds__(256) sgemm_bias_kernel(
    int M, int N, int K,
    const float* __restrict__ A, const float* __restrict__ B,
    const float* __restrict__ bias, float* __restrict__ C)
{
    constexpr int BM = 128, BN = 128, BK = 8, TM = 8, TN = 8;
    __shared__ float As[BK][BM];
    __shared__ float Bs[BK][BN];

    const int tid  = threadIdx.x;
    const int trow = tid >> 4;          // 0..15
    const int tcol = tid & 15;          // 0..15
    const int m0   = blockIdx.y * BM;
    const int n0   = blockIdx.x * BN;

    // load mappings
    const int aRow = tid >> 1;          // 0..127
    const int aCol = (tid & 1) * 4;     // 0 or 4
    const int bRow = tid >> 5;          // 0..7
    const int bCol = (tid & 31) * 4;    // 0..124

    float acc[TM][TN];
#pragma unroll
    for (int i = 0; i < TM; i++)
#pragma unroll
        for (int j = 0; j < TN; j++) acc[i][j] = 0.f;

    for (int k0 = 0; k0 < K; k0 += BK) {
        float4 a4 = *(const float4*)&A[(long)(m0 + aRow) * K + k0 + aCol];
        float4 b4 = *(const float4*)&B[(long)(k0 + bRow) * N + n0 + bCol];
        __syncthreads();
        As[aCol + 0][aRow] = a4.x;
        As[aCol + 1][aRow] = a4.y;
        As[aCol + 2][aRow] = a4.z;
        As[aCol + 3][aRow] = a4.w;
        *(float4*)&Bs[bRow][bCol] = b4;
        __syncthreads();

#pragma unroll
        for (int k = 0; k < BK; k++) {
            float ar[TM], br[TN];
#pragma unroll
            for (int i = 0; i < TM; i++) ar[i] = As[k][trow * TM + i];
#pragma unroll
            for (int j = 0; j < TN; j++) br[j] = Bs[k][tcol * TN + j];
#pragma unroll
            for (int i = 0; i < TM; i++)
#pragma unroll
                for (int j = 0; j < TN; j++) acc[i][j] += ar[i] * br[j];
        }
    }

#pragma unroll
    for (int i = 0; i < TM; i++) {
        const int gm = m0 + trow * TM + i;
#pragma unroll
        for (int j = 0; j < TN; j += 4) {
            const int gn = n0 + tcol * TN + j;
            float4 o;
            o.x = acc[i][j + 0] + bias[gn + 0];
            o.y = acc[i][j + 1] + bias[gn + 1];
            o.z = acc[i][j + 2] + bias[gn + 2];
            o.w = acc[i][j + 3] + bias[gn + 3];
            *(float4*)&C[(long)gm * N + gn] = o;
        }
    }
}

// ---------------------------------------------------------------------------
// Flash-style attention (no causal mask, per the reference):
//   scores = Q K^T (UNscaled), att = softmax(scores), y = (att @ V) / sqrt(D)
// One block handles BQ=64 queries of one (b,h); loops over 64-key tiles.
// Thread mapping: row = tid/4 (query row), cg = tid%4.
//   S-stage: thread owns s[jj] for key j = cg + 4*jj  (conflict-free K float4 reads)
//   O-stage: thread owns output cols c = cg*16 .. cg*16+15
// P tile is exchanged through SMEM; row-quad lives in one warp -> __syncwarp.
// ---------------------------------------------------------------------------
#define AT_BQ  64
#define AT_BK  64
#define AT_LD  (DH + 4)       // 68: padded row stride
#define AT_SMEM_FLOATS (4 * AT_BQ * AT_LD)
#define AT_SMEM_BYTES  (AT_SMEM_FLOATS * 4)

__global__ void __launch_bounds__(256) attn_kernel(
    const float* __restrict__ qkv, float* __restrict__ y)
{
    extern __shared__ float sm[];
    float* Qs = sm;                       // [64][68]
    float* Ks = Qs + AT_BQ * AT_LD;       // [64][68]
    float* Vs = Ks + AT_BK * AT_LD;       // [64][68]
    float* Ps = Vs + AT_BK * AT_LD;       // [64][68]

    const int tid = threadIdx.x;
    const int bh  = blockIdx.y;
    const int b   = bh >> 4;
    const int h   = bh & 15;
    const int q0  = blockIdx.x * AT_BQ;
    const int row = tid >> 2;             // 0..63
    const int cg  = tid & 3;              // 0..3
    const int base = b * TT * C3;         // fits in int (12.6M)
    const int hoff = h * DH;

    // ---- load Q tile (64 x 64) ----
    for (int i = tid; i < AT_BQ * DH / 4; i += 256) {
        const int r = i >> 4;
        const int c = (i & 15) * 4;
        float4 v = *(const float4*)&qkv[base + (q0 + r) * C3 + hoff + c];
        *(float4*)&Qs[r * AT_LD + c] = v;
    }

    float m_i = -1e30f, l_i = 0.f;
    float o[16];
#pragma unroll
    for (int c = 0; c < 16; c++) o[c] = 0.f;

    for (int j0 = 0; j0 < TT; j0 += AT_BK) {
        __syncthreads();  // previous O-stage done with Vs
        // ---- load K & V tiles ----
        for (int i = tid; i < AT_BK * DH / 4; i += 256) {
            const int r = i >> 4;
            const int c = (i & 15) * 4;
            const int tok = base + (j0 + r) * C3 + hoff;
            *(float4*)&Ks[r * AT_LD + c] = *(const float4*)&qkv[tok + CC + c];
            *(float4*)&Vs[r * AT_LD + c] = *(const float4*)&qkv[tok + 2 * CC + c];
        }
        __syncthreads();

        // ---- S stage: s[jj] = Q[row] . K[cg + 4*jj] ----
        float s[16];
#pragma unroll
        for (int jj = 0; jj < 16; jj++) s[jj] = 0.f;
#pragma unroll 4
        for (int d = 0; d < DH; d += 4) {
            float4 q = *(const float4*)&Qs[row * AT_LD + d];
#pragma unroll
            for (int jj = 0; jj < 16; jj++) {
                float4 kv = *(const float4*)&Ks[(cg + 4 * jj) * AT_LD + d];
                s[jj] += q.x * kv.x + q.y * kv.y + q.z * kv.z + q.w * kv.w;
            }
        }

        // ---- online softmax (row reduction over the 4-lane quad) ----
        float mt = s[0];
#pragma unroll
        for (int jj = 1; jj < 16; jj++) mt = fmaxf(mt, s[jj]);
        mt = fmaxf(mt, __shfl_xor_sync(0xffffffffu, mt, 1));
        mt = fmaxf(mt, __shfl_xor_sync(0xffffffffu, mt, 2));
        const float m_new = fmaxf(m_i, mt);
        const float scale = __expf(m_i - m_new);

        float lt = 0.f;
#pragma unroll
        for (int jj = 0; jj < 16; jj++) {
            const float p = __expf(s[jj] - m_new);
            lt += p;
            Ps[row * AT_LD + cg + 4 * jj] = p;
        }
        lt += __shfl_xor_sync(0xffffffffu, lt, 1);
        lt += __shfl_xor_sync(0xffffffffu, lt, 2);
        l_i = l_i * scale + lt;
        m_i = m_new;
#pragma unroll
        for (int c = 0; c < 16; c++) o[c] *= scale;
        __syncwarp();  // Ps visible within the row-quad's warp

        // ---- O stage: o[c] += P[row][j] * V[j][cg*16 + c] ----
        const int c0 = cg * 16;
#pragma unroll 4
        for (int j = 0; j < AT_BK; j++) {
            const float p = Ps[row * AT_LD + j];
            const float* vr = &Vs[j * AT_LD + c0];
            float4 v0 = *(const float4*)&vr[0];
            float4 v1 = *(const float4*)&vr[4];
            float4 v2 = *(const float4*)&vr[8];
            float4 v3 = *(const float4*)&vr[12];
            o[0]  += p * v0.x; o[1]  += p * v0.y; o[2]  += p * v0.z; o[3]  += p * v0.w;
            o[4]  += p * v1.x; o[5]  += p * v1.y; o[6]  += p * v1.z; o[7]  += p * v1.w;
            o[8]  += p * v2.x; o[9]  += p * v2.y; o[10] += p * v2.z; o[11] += p * v2.w;
            o[12] += p * v3.x; o[13] += p * v3.y; o[14] += p * v3.z; o[15] += p * v3.w;
        }
        __syncwarp();  // done reading Ps before next tile's writes
    }

    // ---- epilogue: normalize by softmax sum and /sqrt(64) ----
    const float inv = 1.0f / (l_i * 8.0f);
    float* yp = &y[(b * TT + q0 + row) * CC + hoff + cg * 16];
#pragma unroll
    for (int c = 0; c < 16; c += 4) {
        float4 ov;
        ov.x = o[c + 0] * inv;
        ov.y = o[c + 1] * inv;
        ov.z = o[c + 2] * inv;
        ov.w = o[c + 3] * inv;
        *(float4*)&yp[c] = ov;
    }
}

// ---------------------------------------------------------------------------
// Launch
// ---------------------------------------------------------------------------
extern "C" void kernel_launch(void* const* d_in, const int* in_sizes, int n_in,
                              void* d_out, int out_size)
{
    const float* x      = (const float*)d_in[0];
    const float* W_attn = (const float*)d_in[1];
    const float* b_attn = (const float*)d_in[2];
    const float* W_proj = (const float*)d_in[3];
    const float* b_proj = (const float*)d_in[4];
    float* out = (float*)d_out;

    float* qkv = nullptr;
    float* yb  = nullptr;
    cudaGetSymbolAddress((void**)&qkv, g_qkv);
    cudaGetSymbolAddress((void**)&yb,  g_y);

    cudaFuncSetAttribute(attn_kernel,
                         cudaFuncAttributeMaxDynamicSharedMemorySize,
                         AT_SMEM_BYTES);

    // 1) QKV = x @ W_attn + b_attn        (4096 x 3072 x 1024)
    sgemm_bias_kernel<<<dim3(C3 / 128, NTOK / 128), 256>>>(
        NTOK, C3, CC, x, W_attn, b_attn, qkv);

    // 2) attention -> y (already in (b,t,h*d) layout)
    attn_kernel<<<dim3(TT / AT_BQ, BB * NH), 256, AT_SMEM_BYTES>>>(qkv, yb);

    // 3) out = y @ W_proj + b_proj        (4096 x 1024 x 1024)
    sgemm_bias_kernel<<<dim3(CC / 128, NTOK / 128), 256>>>(
        NTOK, CC, CC, yb, W_proj, b_proj, out);
}

// round 2
// speedup vs baseline: 2.1247x; 2.1247x over previous
#include <cuda_runtime.h>
#include <cuda_bf16.h>
#include <math.h>
#include <stdint.h>

#define BB   2
#define TT   2048
#define CC   1024
#define NH   16
#define DH   64
#define NTOK (BB * TT)
#define C3   (3 * CC)

// scratch
__device__ float g_qkv[NTOK * C3];
__device__ float g_y[NTOK * CC];

// ---------------------------------------------------------------------------
// helpers
// ---------------------------------------------------------------------------
__device__ __forceinline__ uint32_t f2tf_bits(float x) {
    uint32_t u; asm("cvt.rna.tf32.f32 %0, %1;" : "=r"(u) : "f"(x)); return u;
}
__device__ __forceinline__ float tfr(float x) {
    return __uint_as_float(f2tf_bits(x));
}
__device__ __forceinline__ void split_tf32(float x, float& hi, float& lo) {
    hi = tfr(x);
    lo = tfr(x - hi);
}
// D += A(16x8,row) * B(8x8,col) , tf32 in, fp32 acc
__device__ __forceinline__ void mma_tf32(float* d, const uint32_t* a,
                                         uint32_t b0, uint32_t b1) {
    asm volatile(
        "mma.sync.aligned.m16n8k8.row.col.f32.tf32.tf32.f32 "
        "{%0,%1,%2,%3}, {%4,%5,%6,%7}, {%8,%9}, {%0,%1,%2,%3};"
        : "+f"(d[0]), "+f"(d[1]), "+f"(d[2]), "+f"(d[3])
        : "r"(a[0]), "r"(a[1]), "r"(a[2]), "r"(a[3]), "r"(b0), "r"(b1));
}

// ---------------------------------------------------------------------------
// 3xTF32 GEMM with fused bias: C[M,N] = A[M,K] @ B[K,N] + bias
// BM=BN=128, BK=16, 256 thr (8 warps, 2x4), warp tile 64x32, mma m16n8k8.
// ---------------------------------------------------------------------------
__global__ void __launch_bounds__(256) gemm3x_kernel(
    int M, int N, int K,
    const float* __restrict__ A, const float* __restrict__ B,
    const float* __restrict__ bias, float* __restrict__ C)
{
    __shared__ float Ah[128][20], Al[128][20];   // pad 20: conflict-free frag reads
    __shared__ float Bh[16][136], Bl[16][136];   // pad 136

    const int tid  = threadIdx.x;
    const int wid  = tid >> 5, lane = tid & 31;
    const int gr   = lane >> 2, tg = lane & 3;
    const int wr   = wid >> 2,  wc = wid & 3;
    const int m0   = blockIdx.y * 128;
    const int n0   = blockIdx.x * 128;

    float acc[4][4][4];
#pragma unroll
    for (int i = 0; i < 4; i++)
#pragma unroll
        for (int j = 0; j < 4; j++)
#pragma unroll
            for (int r = 0; r < 4; r++) acc[i][j][r] = 0.f;

    for (int k0 = 0; k0 < K; k0 += 16) {
        __syncthreads();
        // A tile 128x16
#pragma unroll
        for (int p = 0; p < 2; p++) {
            const int f = tid + p * 256;
            const int r = f >> 2, c = (f & 3) << 2;
            float4 v = *(const float4*)&A[(long)(m0 + r) * K + k0 + c];
            float h, l;
            split_tf32(v.x, h, l); Ah[r][c + 0] = h; Al[r][c + 0] = l;
            split_tf32(v.y, h, l); Ah[r][c + 1] = h; Al[r][c + 1] = l;
            split_tf32(v.z, h, l); Ah[r][c + 2] = h; Al[r][c + 2] = l;
            split_tf32(v.w, h, l); Ah[r][c + 3] = h; Al[r][c + 3] = l;
        }
        // B tile 16x128
#pragma unroll
        for (int p = 0; p < 2; p++) {
            const int f = tid + p * 256;
            const int r = f >> 5, c = (f & 31) << 2;
            float4 v = *(const float4*)&B[(long)(k0 + r) * N + n0 + c];
            float h, l;
            split_tf32(v.x, h, l); Bh[r][c + 0] = h; Bl[r][c + 0] = l;
            split_tf32(v.y, h, l); Bh[r][c + 1] = h; Bl[r][c + 1] = l;
            split_tf32(v.z, h, l); Bh[r][c + 2] = h; Bl[r][c + 2] = l;
            split_tf32(v.w, h, l); Bh[r][c + 3] = h; Bl[r][c + 3] = l;
        }
        __syncthreads();

#pragma unroll
        for (int ks = 0; ks < 2; ks++) {
            const int kk = ks * 8;
            uint32_t ah[4][4], al[4][4];
#pragma unroll
            for (int mt = 0; mt < 4; mt++) {
                const int rb = wr * 64 + mt * 16;
                ah[mt][0] = __float_as_uint(Ah[rb + gr    ][kk + tg    ]);
                ah[mt][1] = __float_as_uint(Ah[rb + gr + 8][kk + tg    ]);
                ah[mt][2] = __float_as_uint(Ah[rb + gr    ][kk + tg + 4]);
                ah[mt][3] = __float_as_uint(Ah[rb + gr + 8][kk + tg + 4]);
                al[mt][0] = __float_as_uint(Al[rb + gr    ][kk + tg    ]);
                al[mt][1] = __float_as_uint(Al[rb + gr + 8][kk + tg    ]);
                al[mt][2] = __float_as_uint(Al[rb + gr    ][kk + tg + 4]);
                al[mt][3] = __float_as_uint(Al[rb + gr + 8][kk + tg + 4]);
            }
#pragma unroll
            for (int nt = 0; nt < 4; nt++) {
                const int cb = wc * 32 + nt * 8 + gr;
                const uint32_t bh0 = __float_as_uint(Bh[kk + tg    ][cb]);
                const uint32_t bh1 = __float_as_uint(Bh[kk + tg + 4][cb]);
                const uint32_t bl0 = __float_as_uint(Bl[kk + tg    ][cb]);
                const uint32_t bl1 = __float_as_uint(Bl[kk + tg + 4][cb]);
#pragma unroll
                for (int mt = 0; mt < 4; mt++) {
                    mma_tf32(acc[mt][nt], ah[mt], bh0, bh1);
                    mma_tf32(acc[mt][nt], ah[mt], bl0, bl1);
                    mma_tf32(acc[mt][nt], al[mt], bh0, bh1);
                }
            }
        }
    }

#pragma unroll
    for (int nt = 0; nt < 4; nt++) {
        const int col = n0 + wc * 32 + nt * 8 + tg * 2;
        const float2 bv = *(const float2*)&bias[col];
#pragma unroll
        for (int mt = 0; mt < 4; mt++) {
            const int row = m0 + wr * 64 + mt * 16 + gr;
            float2 o0 = make_float2(acc[mt][nt][0] + bv.x, acc[mt][nt][1] + bv.y);
            float2 o1 = make_float2(acc[mt][nt][2] + bv.x, acc[mt][nt][3] + bv.y);
            *(float2*)&C[(long)row * N + col]       = o0;
            *(float2*)&C[(long)(row + 8) * N + col] = o1;
        }
    }
}

// ---------------------------------------------------------------------------
// Attention (full softmax, unscaled scores, /8 at the end):
// block = 64 queries of one (b,h), 128 thr (4 warps; warp w -> rows 16w..).
// S = QK^T via 3xTF32 (K tile split in smem, Q split in regs).
// PV via plain tf32 (P tf32-rounded in smem, V frags straight from gmem).
// ---------------------------------------------------------------------------
#define ALD 68
#define AT_SMEM_BYTES (3 * 64 * ALD * 4)

__global__ void __launch_bounds__(128) attn3x_kernel(
    const float* __restrict__ qkv, float* __restrict__ y)
{
    extern __shared__ float sm[];
    float* Kh = sm;
    float* Kl = sm + 64 * ALD;
    float* Ps = sm + 2 * 64 * ALD;

    const int tid  = threadIdx.x;
    const int wid  = tid >> 5, lane = tid & 31;
    const int gr   = lane >> 2, tg = lane & 3;
    const int bh   = blockIdx.y;
    const int b    = bh >> 4, h = bh & 15;
    const int q0   = blockIdx.x * 64;
    const int base = b * TT * C3;
    const int hoff = h * DH;
    const int qr   = q0 + wid * 16;

    // Q fragments (split) in registers
    uint32_t qh[8][4], ql[8][4];
    {
        const float* Qp = &qkv[base + hoff];
#pragma unroll
        for (int kt = 0; kt < 8; kt++) {
            const int c0 = kt * 8 + tg;
            float v[4];
            v[0] = Qp[(qr + gr)     * C3 + c0];
            v[1] = Qp[(qr + gr + 8) * C3 + c0];
            v[2] = Qp[(qr + gr)     * C3 + c0 + 4];
            v[3] = Qp[(qr + gr + 8) * C3 + c0 + 4];
#pragma unroll
            for (int r = 0; r < 4; r++) {
                float hi, lo;
                split_tf32(v[r], hi, lo);
                qh[kt][r] = __float_as_uint(hi);
                ql[kt][r] = __float_as_uint(lo);
            }
        }
    }

    float oacc[8][4];
#pragma unroll
    for (int nt = 0; nt < 8; nt++)
#pragma unroll
        for (int r = 0; r < 4; r++) oacc[nt][r] = 0.f;
    float mA = -1e30f, mB = -1e30f, lA = 0.f, lB = 0.f;

    for (int jt = 0; jt < 32; jt++) {
        const int j0 = jt * 64;
        __syncthreads();
        // K tile 64x64 -> split smem
#pragma unroll
        for (int p = 0; p < 8; p++) {
            const int f = tid + p * 128;
            const int r = f >> 4, c = (f & 15) << 2;
            float4 v = *(const float4*)&qkv[base + (j0 + r) * C3 + CC + hoff + c];
            float4 hv, lv;
            split_tf32(v.x, hv.x, lv.x);
            split_tf32(v.y, hv.y, lv.y);
            split_tf32(v.z, hv.z, lv.z);
            split_tf32(v.w, hv.w, lv.w);
            *(float4*)&Kh[r * ALD + c] = hv;
            *(float4*)&Kl[r * ALD + c] = lv;
        }
        __syncthreads();

        // ---- S = Q K^T (3xTF32) ----
        float sacc[8][4];
#pragma unroll
        for (int nt = 0; nt < 8; nt++)
#pragma unroll
            for (int r = 0; r < 4; r++) sacc[nt][r] = 0.f;

#pragma unroll
        for (int kt = 0; kt < 8; kt++) {
            const int kc = kt * 8 + tg;
#pragma unroll
            for (int nt = 0; nt < 8; nt++) {
                const int nr = (nt * 8 + gr) * ALD;
                const uint32_t bh0 = __float_as_uint(Kh[nr + kc]);
                const uint32_t bh1 = __float_as_uint(Kh[nr + kc + 4]);
                const uint32_t bl0 = __float_as_uint(Kl[nr + kc]);
                const uint32_t bl1 = __float_as_uint(Kl[nr + kc + 4]);
                mma_tf32(sacc[nt], qh[kt], bh0, bh1);
                mma_tf32(sacc[nt], qh[kt], bl0, bl1);
                mma_tf32(sacc[nt], ql[kt], bh0, bh1);
            }
        }

        // ---- online softmax ----
        float mtA = -1e30f, mtB = -1e30f;
#pragma unroll
        for (int nt = 0; nt < 8; nt++) {
            mtA = fmaxf(mtA, fmaxf(sacc[nt][0], sacc[nt][1]));
            mtB = fmaxf(mtB, fmaxf(sacc[nt][2], sacc[nt][3]));
        }
        mtA = fmaxf(mtA, __shfl_xor_sync(0xffffffffu, mtA, 1));
        mtA = fmaxf(mtA, __shfl_xor_sync(0xffffffffu, mtA, 2));
        mtB = fmaxf(mtB, __shfl_xor_sync(0xffffffffu, mtB, 1));
        mtB = fmaxf(mtB, __shfl_xor_sync(0xffffffffu, mtB, 2));
        const float mnA = fmaxf(mA, mtA), mnB = fmaxf(mB, mtB);
        const float scA = __expf(mA - mnA), scB = __expf(mB - mnB);

        float ltA = 0.f, ltB = 0.f;
        const int prA = (wid * 16 + gr) * ALD;
        const int prB = prA + 8 * ALD;
#pragma unroll
        for (int nt = 0; nt < 8; nt++) {
            const float p0 = __expf(sacc[nt][0] - mnA);
            const float p1 = __expf(sacc[nt][1] - mnA);
            const float p2 = __expf(sacc[nt][2] - mnB);
            const float p3 = __expf(sacc[nt][3] - mnB);
            ltA += p0 + p1; ltB += p2 + p3;
            const int cc = nt * 8 + tg * 2;
            *(float2*)&Ps[prA + cc] = make_float2(tfr(p0), tfr(p1));
            *(float2*)&Ps[prB + cc] = make_float2(tfr(p2), tfr(p3));
        }
        ltA += __shfl_xor_sync(0xffffffffu, ltA, 1);
        ltA += __shfl_xor_sync(0xffffffffu, ltA, 2);
        ltB += __shfl_xor_sync(0xffffffffu, ltB, 1);
        ltB += __shfl_xor_sync(0xffffffffu, ltB, 2);
        lA = lA * scA + ltA; lB = lB * scB + ltB;
        mA = mnA; mB = mnB;
#pragma unroll
        for (int nt = 0; nt < 8; nt++) {
            oacc[nt][0] *= scA; oacc[nt][1] *= scA;
            oacc[nt][2] *= scB; oacc[nt][3] *= scB;
        }

        // ---- O += P V (plain tf32; V frags from gmem) ----
#pragma unroll
        for (int kt = 0; kt < 8; kt++) {
            uint32_t pa[4];
            const int pp = (wid * 16 + gr) * ALD + kt * 8 + tg;
            pa[0] = __float_as_uint(Ps[pp]);
            pa[1] = __float_as_uint(Ps[pp + 8 * ALD]);
            pa[2] = __float_as_uint(Ps[pp + 4]);
            pa[3] = __float_as_uint(Ps[pp + 8 * ALD + 4]);
            const float* v0 = &qkv[base + (j0 + kt * 8 + tg) * C3 + 2 * CC + hoff];
            const float* v4 = v0 + 4 * C3;
#pragma unroll
            for (int nt = 0; nt < 8; nt++) {
                const uint32_t b0 = f2tf_bits(v0[nt * 8 + gr]);
                const uint32_t b1 = f2tf_bits(v4[nt * 8 + gr]);
                mma_tf32(oacc[nt], pa, b0, b1);
            }
        }
    }

    // epilogue: /l and /sqrt(64)
    const float invA = 1.0f / (lA * 8.0f);
    const float invB = 1.0f / (lB * 8.0f);
#pragma unroll
    for (int nt = 0; nt < 8; nt++) {
        const int cc = nt * 8 + tg * 2;
        *(float2*)&y[(b * TT + qr + gr) * CC + hoff + cc] =
            make_float2(oacc[nt][0] * invA, oacc[nt][1] * invA);
        *(float2*)&y[(b * TT + qr + gr + 8) * CC + hoff + cc] =
            make_float2(oacc[nt][2] * invB, oacc[nt][3] * invB);
    }
}

// ---------------------------------------------------------------------------
extern "C" void kernel_launch(void* const* d_in, const int* in_sizes, int n_in,
                              void* d_out, int out_size)
{
    const float* x      = (const float*)d_in[0];
    const float* W_attn = (const float*)d_in[1];
    const float* b_attn = (const float*)d_in[2];
    const float* W_proj = (const float*)d_in[3];
    const float* b_proj = (const float*)d_in[4];
    float* out = (float*)d_out;

    float* qkv = nullptr;
    float* yb  = nullptr;
    cudaGetSymbolAddress((void**)&qkv, g_qkv);
    cudaGetSymbolAddress((void**)&yb,  g_y);

    cudaFuncSetAttribute(attn3x_kernel,
                         cudaFuncAttributeMaxDynamicSharedMemorySize,
                         AT_SMEM_BYTES);

    gemm3x_kernel<<<dim3(C3 / 128, NTOK / 128), 256>>>(
        NTOK, C3, CC, x, W_attn, b_attn, qkv);

    attn3x_kernel<<<dim3(TT / 64, BB * NH), 128, AT_SMEM_BYTES>>>(qkv, yb);

    gemm3x_kernel<<<dim3(CC / 128, NTOK / 128), 256>>>(
        NTOK, CC, CC, yb, W_proj, b_proj, out);
}